// round 7
// baseline (speedup 1.0000x reference)
#include <cuda_runtime.h>
#include <cstdint>

// DetectPeaksTM: per-row sliding max (K=301) NMS + top-2 (value, index).
// Candidate-based: a survivor must equal the max of its aligned 128-tile
// (tile fully inside the +-150 window). 4 rows per CTA: phase 1 streams all
// rows (tile maxima only), then warps 0..3 run the 4 selections in parallel,
// amortizing the serial selection tail 4x.

#define NT    8192
#define HALF  150
#define WIN   301
#define RPB   4          // rows per block

typedef unsigned long long u64;
typedef unsigned int u32;

__device__ __forceinline__ u32 absbits(float f) {
    return __float_as_uint(f) & 0x7fffffffu;
}
__device__ __forceinline__ u64 umax64(u64 a, u64 b) { return a > b ? a : b; }
__device__ __forceinline__ u64 shfl_xor_u64(u64 v, int d) {
    u32 lo = (u32)v, hi = (u32)(v >> 32);
    lo = __shfl_xor_sync(0xffffffffu, lo, d);
    hi = __shfl_xor_sync(0xffffffffu, hi, d);
    return ((u64)hi << 32) | lo;
}

// First index > bound inside tile whose absbits == val, or -1.
__device__ __forceinline__ int find_next(u32 em, int tile, int bound, int lane) {
    int base = tile * 128 + lane * 4;
    int rel = bound - base;                  // element j excluded iff j <= rel
    u32 emm = em;
    if (rel >= 3) emm = 0;
    else if (rel >= 0) emm &= (0xFu << (rel + 1));
    u32 bl = __ballot_sync(0xffffffffu, emm != 0);
    if (!bl) return -1;
    int lf = __ffs((int)bl) - 1;
    u32 pk = __shfl_sync(0xffffffffu, emm, lf);
    return tile * 128 + lf * 4 + (__ffs((int)pk) - 1);
}

__global__ void __launch_bounds__(512)
detect_peaks_kernel(const float* __restrict__ x, float* __restrict__ out, int nrows) {
    __shared__ u32 tileMax[RPB][64];

    const int tid  = threadIdx.x;
    const int lane = tid & 31;
    const int warp = tid >> 5;
    const u32 FULL = 0xffffffffu;
    const int row0 = blockIdx.x * RPB;

    // ---- phase 1: stream RPB rows, per-128-tile max of |x| ----
#pragma unroll
    for (int r = 0; r < RPB; r++) {
        const float4* src = (const float4*)(x + (size_t)(row0 + r) * NT);
        float4 v[4];
#pragma unroll
        for (int k = 0; k < 4; k++) v[k] = src[tid + 512 * k];
#pragma unroll
        for (int k = 0; k < 4; k++) {
            float m01 = fmaxf(fabsf(v[k].x), fabsf(v[k].y));
            float m23 = fmaxf(fabsf(v[k].z), fabsf(v[k].w));
            float m   = fmaxf(m01, m23);
            u32 m1 = __reduce_max_sync(FULL, __float_as_uint(m));
            if (lane == 0) tileMax[r][warp + 16 * k] = m1;
        }
    }
    __syncthreads();

    if (warp >= RPB) return;

    // ---- phase 2: warp w selects for row row0+w ----
    const int row = row0 + warp;
    const float* xr = x + (size_t)row * NT;
    const u32* tmx = tileMax[warp];

    u64 keys[2];
#pragma unroll
    for (int q = 0; q < 2; q++) {
        int t = lane + 32 * q;
        keys[q] = ((u64)tmx[t] << 32) | (u32)(~(u32)(t * 128));
    }
    u64 pend = 0;        // at most one pending same-value occurrence (uniform)
    int pendIdx = -1;

    float rv0 = 0.0f, rv1 = 0.0f;
    int   ri0 = 0,    ri1 = 0;
    int found = 0;

    for (int it = 0; it < 192 && found < 2; it++) {
        u64 best = umax64(umax64(keys[0], keys[1]), pend);
#pragma unroll
        for (int s = 16; s > 0; s >>= 1) best = umax64(best, shfl_xor_u64(best, s));
        if (best == 0ull) break;

        bool wasPend = (best == pend && pend != 0ull);
        if (wasPend) pend = 0;
        if (keys[0] == best) keys[0] = 0;
        if (keys[1] == best) keys[1] = 0;

        u32 val = (u32)(best >> 32);
        int tile, idxV;
        if (wasPend) { idxV = pendIdx; tile = idxV >> 7; }
        else         { tile = (int)((~(u32)(best & 0xffffffffull)) >> 7); idxV = -1; }

        // rescan tile for occurrence chain (L1/L2-hot)
        float4 tv = ((const float4*)(xr + tile * 128))[lane];
        u32 em = (u32)(absbits(tv.x) == val)        |
                 ((u32)(absbits(tv.y) == val) << 1) |
                 ((u32)(absbits(tv.z) == val) << 2) |
                 ((u32)(absbits(tv.w) == val) << 3);
        if (!wasPend) idxV = find_next(em, tile, tile * 128 - 1, lane);
        int nxt = find_next(em, tile, idxV, lane);
        if (nxt >= 0) { pend = ((u64)val << 32) | (u32)(~(u32)nxt); pendIdx = nxt; }

        // verify idxV against window max using tile bounds (smem)
        int lo = max(idxV - HALF, 0);
        int hi = min(idxV + HALF, NT - 1);
        int ta = lo >> 7, tb = hi >> 7;
        int t = ta + lane;
        u32 tm = (t <= tb) ? tmx[t] : 0u;
        u32 bound = __reduce_max_sync(FULL, tm);

        bool accept = (bound <= val);
        if (!accept) {
            bool fullt = (t <= tb) && (t * 128 >= lo) && (t * 128 + 127 <= hi);
            if (__reduce_max_sync(FULL, fullt ? tm : 0u) > val) continue;
            // ambiguous edge tiles: exact window max from gmem (rare)
            u32 mb = 0;
            int base = idxV - HALF;
#pragma unroll
            for (int rr = 0; rr < 10; rr++) {
                int off = lane + 32 * rr;
                int p = min(max(base + off, 0), NT - 1);
                u32 xb = absbits(__ldg(xr + p));
                if (off < WIN) mb = max(mb, xb);
            }
            if (__reduce_max_sync(FULL, mb) > val) continue;
            accept = true;
        }

        if (found == 0) { rv0 = __uint_as_float(val); ri0 = idxV; }
        else            { rv1 = __uint_as_float(val); ri1 = idxV; }
        found++;
    }

    if (lane == 0) {
        if (found < 2) {                 // <2 survivors: next-best score is 0
            rv1 = 0.0f;
            ri1 = (found >= 1 && ri0 == 0) ? 1 : 0;
        }
        out[row * 2 + 0] = rv0;
        out[row * 2 + 1] = rv1;
        out[(size_t)nrows * 2 + row * 2 + 0] = (float)ri0;
        out[(size_t)nrows * 2 + row * 2 + 1] = (float)ri1;
    }
}

extern "C" void kernel_launch(void* const* d_in, const int* in_sizes, int n_in,
                              void* d_out, int out_size) {
    const float* x = (const float*)d_in[0];
    float* out = (float*)d_out;
    int nrows = in_sizes[0] / NT;   // 6144
    detect_peaks_kernel<<<nrows / RPB, 512>>>(x, out, nrows);
}